// round 15
// baseline (speedup 1.0000x reference)
#include <cuda_runtime.h>
#include <cstddef>

// ---------------------------------------------------------------------------
// Depthwise Gaussian blur, sigma=7, K=29, reflect padding, (8,64,256,256) f32.
// Separable, fused single kernel. TY=32, 3 CTAs/SM (R7).
// R10 change: fma.rn.f32x2 packed FMA (Blackwell) in phases 2 and 3:
//  - phase 2: float4 acc/operand = 2 native f32x2 pairs; 464 FFMA2 vs 928 FFMA
//  - phase 3: 2 rows per lane-iteration, pairs packed across rows, chunked
//    diagonal tap order; 232 FFMA2 per 2 rows vs 464 FFMA
// Bitwise-identical results to scalar FFMA (IEEE fused both ways).
// ---------------------------------------------------------------------------

#define IMG_H   256
#define IMG_W   256
#define TY      32            // output rows per tile
#define RAD     14
#define IR      (TY + 2*RAD)  // 60 input rows in smem
#define PITCH   288           // floats per smem row (16 halo + 256 + 16 halo)
#define XOFF    16            // float offset of x=0 within a smem row
#define SMEM_BYTES (IR * PITCH * 4)   // 69120

// Quad swizzle: XOR float-offset bit2 with bit5 (bijective, float4-preserving).
__device__ __forceinline__ int swz(int o) { return o ^ ((o & 32) >> 3); }

// ---- f32x2 packed-math helpers (sm_103a) ----------------------------------
__device__ __forceinline__ unsigned long long pack2s(float w) {
    unsigned long long r;
    asm("mov.b64 %0, {%1, %1};" : "=l"(r) : "f"(w));
    return r;
}
__device__ __forceinline__ unsigned long long pack2f(float x, float y) {
    unsigned long long r;
    asm("mov.b64 %0, {%1, %2};" : "=l"(r) : "f"(x), "f"(y));
    return r;
}
__device__ __forceinline__ void unpack2(float& x, float& y, unsigned long long p) {
    asm("mov.b64 {%0, %1}, %2;" : "=f"(x), "=f"(y) : "l"(p));
}
__device__ __forceinline__ void ffma2(unsigned long long& d,
                                      unsigned long long a, unsigned long long b) {
    asm("fma.rn.f32x2 %0, %1, %2, %0;" : "+l"(d) : "l"(a), "l"(b));
}

// Unnormalized Gaussian g(d) = exp(-d^2/98), d = 0..14 (double literals).
constexpr double GV0  = 1.0;
constexpr double GV1  = 0.98984780;
constexpr double GV2  = 0.96000544;
constexpr double GV3  = 0.91225408;
constexpr double GV4  = 0.84936582;
constexpr double GV5  = 0.77483743;
constexpr double GV6  = 0.69256933;
constexpr double GV7  = 0.60653066;
constexpr double GV8  = 0.52045018;
constexpr double GV9  = 0.43756464;
constexpr double GV10 = 0.36044780;
constexpr double GV11 = 0.29092383;
constexpr double GV12 = 0.23006630;
constexpr double GV13 = 0.17826390;
constexpr double GV14 = 0.13533528;

constexpr double GSUM = GV0 + 2.0*(GV1+GV2+GV3+GV4+GV5+GV6+GV7+GV8+GV9+GV10+GV11+GV12+GV13+GV14);

__device__ constexpr float GW[29] = {
    (float)(GV14/GSUM), (float)(GV13/GSUM), (float)(GV12/GSUM), (float)(GV11/GSUM),
    (float)(GV10/GSUM), (float)(GV9 /GSUM), (float)(GV8 /GSUM), (float)(GV7 /GSUM),
    (float)(GV6 /GSUM), (float)(GV5 /GSUM), (float)(GV4 /GSUM), (float)(GV3 /GSUM),
    (float)(GV2 /GSUM), (float)(GV1 /GSUM), (float)(GV0 /GSUM), (float)(GV1 /GSUM),
    (float)(GV2 /GSUM), (float)(GV3 /GSUM), (float)(GV4 /GSUM), (float)(GV5 /GSUM),
    (float)(GV6 /GSUM), (float)(GV7 /GSUM), (float)(GV8 /GSUM), (float)(GV9 /GSUM),
    (float)(GV10/GSUM), (float)(GV11/GSUM), (float)(GV12/GSUM), (float)(GV13/GSUM),
    (float)(GV14/GSUM)
};

__global__ void __launch_bounds__(256, 3)
gauss29_kernel(const float* __restrict__ x, float* __restrict__ out)
{
    extern __shared__ float S[];   // [IR][PITCH], rows quad-swizzled

    const int tid  = threadIdx.x;
    const int img  = blockIdx.x >> 3;      // 512 images
    const int tile = blockIdx.x & 7;       // 8 row-tiles per image
    const int y0   = tile * TY;

    const float* src = x   + (size_t)img * (IMG_H * IMG_W);
    float*       dst = out + (size_t)img * (IMG_H * IMG_W) + (size_t)y0 * IMG_W;

    // ---------------- Phase 1: load 60 rows with vertical reflect -----------
    #pragma unroll 5
    for (int u = tid; u < IR * 64; u += 256) {
        int r  = u >> 6;
        int c4 = u & 63;
        int gy = y0 - RAD + r;
        gy = (gy < 0) ? -gy : gy;
        gy = (gy > IMG_H - 1) ? (2 * (IMG_H - 1) - gy) : gy;
        float4 v = *((const float4*)(src + (size_t)gy * IMG_W) + c4);
        *(float4*)(&S[r * PITCH + swz(XOFF + c4 * 4)]) = v;
    }
    __syncthreads();

    // ---------------- Phase 2: vertical 29-tap conv, in place, f32x2 --------
    // Each thread: 8 output rows (yr..yr+7) x 1 quad; reads rows yr..yr+35.
    // float4 = two f32x2 pairs -> 2 FFMA2 per (row,tap) instead of 4 FFMA.
    const int xq = tid & 63;          // quad column 0..63
    const int yr = (tid >> 6) * 8;    // 0,8,16,24
    const int colo = swz(XOFF + xq * 4);
    {
        unsigned long long acc2[16];  // [j][half]
        #pragma unroll
        for (int j = 0; j < 16; ++j) acc2[j] = 0ull;   // {0.f,0.f}

        const float* col = &S[yr * PITCH + colo];
        #pragma unroll
        for (int i = 0; i < 36; ++i) {
            ulonglong2 v = *(const ulonglong2*)(col + i * PITCH);
            #pragma unroll
            for (int j = 0; j < 8; ++j) {
                const int k = i - j;               // tap index
                if (k >= 0 && k <= 28) {
                    unsigned long long w2 = pack2s(GW[k]);
                    ffma2(acc2[2*j],     w2, v.x);
                    ffma2(acc2[2*j + 1], w2, v.y);
                }
            }
        }
        __syncthreads();   // all reads done everywhere
        float* od = &S[yr * PITCH + colo];
        #pragma unroll
        for (int j = 0; j < 8; ++j)
            *(ulonglong2*)(od + j * PITCH) =
                make_ulonglong2(acc2[2*j], acc2[2*j + 1]);
        __syncthreads();   // writes visible before phases 2.5/3 read
    }

    // ---------------- Phase 2.5: horizontal reflected halo ------------------
    #pragma unroll 4
    for (int u = tid; u < TY * 32; u += 256) {
        int r = u >> 5;
        int p = u & 31;
        int colidx, xsrc;
        if (p < 16) { colidx = p;                 xsrc = 16 - p;      }
        else        { int q = p - 16; colidx = XOFF + 256 + q; xsrc = 254 - q; }
        S[r * PITCH + swz(colidx)] = S[r * PITCH + swz(XOFF + xsrc)];
    }
    __syncthreads();

    // ---------------- Phase 3: horizontal 29-tap conv, 2 rows/iter, f32x2 ---
    // Lane covers 8 px of TWO rows at once; pair = {row0, row1} value.
    // Window floats i = 0..39 (xi = 8*lane - 16 + i), processed in 5 chunks
    // of 8; per chunk, pairs m[t] are reused by up to 8 taps (diagonals).
    // a2[p] = { out_row0[px p], out_row1[px p] }.
    const int lane = tid & 31;
    const int warp = tid >> 5;        // 0..7
    #pragma unroll 1
    for (int it = 0; it < 2; ++it) {
        const int row0 = warp * 4 + it * 2;      // 0..30 even
        const float* r0 = &S[row0 * PITCH];
        const float* r1 = &S[(row0 + 1) * PITCH];

        unsigned long long a2[8];
        #pragma unroll
        for (int p = 0; p < 8; ++p) a2[p] = 0ull;

        #pragma unroll
        for (int c = 0; c < 5; ++c) {
            const int o = 8 * lane + 8 * c;      // in-row float offset of chunk
            float4 v0a = *(const float4*)(r0 + swz(o));
            float4 v0b = *(const float4*)(r0 + swz(o + 4));
            float4 v1a = *(const float4*)(r1 + swz(o));
            float4 v1b = *(const float4*)(r1 + swz(o + 4));

            unsigned long long m[8];
            m[0] = pack2f(v0a.x, v1a.x); m[1] = pack2f(v0a.y, v1a.y);
            m[2] = pack2f(v0a.z, v1a.z); m[3] = pack2f(v0a.w, v1a.w);
            m[4] = pack2f(v0b.x, v1b.x); m[5] = pack2f(v0b.y, v1b.y);
            m[6] = pack2f(v0b.z, v1b.z); m[7] = pack2f(v0b.w, v1b.w);

            // diagonals d = t - p ; tap k = 8c + d - 2
            #pragma unroll
            for (int d = -7; d <= 7; ++d) {
                const int k = 8 * c + d - 2;
                if (k >= 0 && k <= 28) {
                    unsigned long long w2 = pack2s(GW[k]);
                    #pragma unroll
                    for (int p = 0; p < 8; ++p) {
                        const int t = p + d;
                        if (t >= 0 && t < 8)
                            ffma2(a2[p], w2, m[t]);
                    }
                }
            }
        }

        float o0[8], o1[8];
        #pragma unroll
        for (int p = 0; p < 8; ++p) unpack2(o0[p], o1[p], a2[p]);

        float* w0 = dst + (size_t)row0 * IMG_W + lane * 8;
        float* w1 = w0 + IMG_W;
        *(float4*)(w0 + 0) = make_float4(o0[0], o0[1], o0[2], o0[3]);
        *(float4*)(w0 + 4) = make_float4(o0[4], o0[5], o0[6], o0[7]);
        *(float4*)(w1 + 0) = make_float4(o1[0], o1[1], o1[2], o1[3]);
        *(float4*)(w1 + 4) = make_float4(o1[4], o1[5], o1[6], o1[7]);
    }
}

extern "C" void kernel_launch(void* const* d_in, const int* in_sizes, int n_in,
                              void* d_out, int out_size)
{
    const float* x = (const float*)d_in[0];
    float* out = (float*)d_out;

    const int images = in_sizes[0] / (IMG_H * IMG_W);   // 512
    const int grid = images * 8;                        // 4096 CTAs

    cudaFuncSetAttribute(gauss29_kernel,
                         cudaFuncAttributeMaxDynamicSharedMemorySize,
                         SMEM_BYTES);
    gauss29_kernel<<<grid, 256, SMEM_BYTES>>>(x, out);
}

// round 17
// speedup vs baseline: 1.0225x; 1.0225x over previous
#include <cuda_runtime.h>
#include <cstddef>

// ---------------------------------------------------------------------------
// Depthwise Gaussian blur, sigma=7, K=29, reflect padding, (8,64,256,256) f32.
// Separable, fused single kernel. TY=32, 3 CTAs/SM. ALL-SCALAR FFMA (f32x2
// packed math reverted: R15 showed ptxas lowers it to same-rate FFMA + alu
// packs -> regression).
// R15 change: cut smem bytes (the measured bottleneck, L1=68%):
//  - swz2 swizzle (XOR offset bits 5,6 into quad bits 2,3): conflict-free for
//    4-float, 2-float and 16-float lane strides (all phases verified).
//  - phase 2: 16 rows x float2 per thread -> vertical read amp 4.5x -> 2.75x.
//  - phase 3: 16 px/lane, 12 LDS.128 per 16 px (was 20), chunked diagonals.
// Per-CTA smem traffic 421KB -> 298KB (-29%).
// ---------------------------------------------------------------------------

#define IMG_H   256
#define IMG_W   256
#define TY      32            // output rows per tile
#define RAD     14
#define IR      (TY + 2*RAD)  // 60 input rows in smem
#define PITCH   288           // floats per smem row (16 halo + 256 + 16 halo)
#define XOFF    16            // float offset of x=0 within a smem row
#define SMEM_BYTES (IR * PITCH * 4)   // 69120

// Quad swizzle: XOR float-offset bits 5,6 into bits 2,3 (whole-quad moves,
// bijective within each 32-quad span, float2/float4-alignment preserving).
__device__ __forceinline__ int swz2(int o) { return o ^ ((o & 0x60) >> 3); }

// Unnormalized Gaussian g(d) = exp(-d^2/98), d = 0..14 (double literals).
constexpr double GV0  = 1.0;
constexpr double GV1  = 0.98984780;
constexpr double GV2  = 0.96000544;
constexpr double GV3  = 0.91225408;
constexpr double GV4  = 0.84936582;
constexpr double GV5  = 0.77483743;
constexpr double GV6  = 0.69256933;
constexpr double GV7  = 0.60653066;
constexpr double GV8  = 0.52045018;
constexpr double GV9  = 0.43756464;
constexpr double GV10 = 0.36044780;
constexpr double GV11 = 0.29092383;
constexpr double GV12 = 0.23006630;
constexpr double GV13 = 0.17826390;
constexpr double GV14 = 0.13533528;

constexpr double GSUM = GV0 + 2.0*(GV1+GV2+GV3+GV4+GV5+GV6+GV7+GV8+GV9+GV10+GV11+GV12+GV13+GV14);

__device__ constexpr float GW[29] = {
    (float)(GV14/GSUM), (float)(GV13/GSUM), (float)(GV12/GSUM), (float)(GV11/GSUM),
    (float)(GV10/GSUM), (float)(GV9 /GSUM), (float)(GV8 /GSUM), (float)(GV7 /GSUM),
    (float)(GV6 /GSUM), (float)(GV5 /GSUM), (float)(GV4 /GSUM), (float)(GV3 /GSUM),
    (float)(GV2 /GSUM), (float)(GV1 /GSUM), (float)(GV0 /GSUM), (float)(GV1 /GSUM),
    (float)(GV2 /GSUM), (float)(GV3 /GSUM), (float)(GV4 /GSUM), (float)(GV5 /GSUM),
    (float)(GV6 /GSUM), (float)(GV7 /GSUM), (float)(GV8 /GSUM), (float)(GV9 /GSUM),
    (float)(GV10/GSUM), (float)(GV11/GSUM), (float)(GV12/GSUM), (float)(GV13/GSUM),
    (float)(GV14/GSUM)
};

__global__ void __launch_bounds__(256, 3)
gauss29_kernel(const float* __restrict__ x, float* __restrict__ out)
{
    extern __shared__ float S[];   // [IR][PITCH], rows quad-swizzled (swz2)

    const int tid  = threadIdx.x;
    const int img  = blockIdx.x >> 3;      // 512 images
    const int tile = blockIdx.x & 7;       // 8 row-tiles per image
    const int y0   = tile * TY;

    const float* src = x   + (size_t)img * (IMG_H * IMG_W);
    float*       dst = out + (size_t)img * (IMG_H * IMG_W) + (size_t)y0 * IMG_W;

    // ---------------- Phase 1: load 60 rows with vertical reflect -----------
    #pragma unroll 5
    for (int u = tid; u < IR * 64; u += 256) {
        int r  = u >> 6;
        int c4 = u & 63;
        int gy = y0 - RAD + r;
        gy = (gy < 0) ? -gy : gy;
        gy = (gy > IMG_H - 1) ? (2 * (IMG_H - 1) - gy) : gy;
        float4 v = *((const float4*)(src + (size_t)gy * IMG_W) + c4);
        *(float4*)(&S[r * PITCH + swz2(XOFF + c4 * 4)]) = v;
    }
    __syncthreads();

    // ---------------- Phase 2: vertical 29-tap conv, in place ---------------
    // Thread = (col-pair, row-group): 128 col-pairs x 2 groups of 16 rows.
    // Group g computes rows g*16..g*16+15, reading rows g*16..g*16+43 (<=59).
    // Read amplification (16+28)/16 = 2.75 (was 4.5). All reads precede the
    // barrier; writes (rows 0..31) never alias later reads (phase 3 reads
    // only rows < TY, re-written here; rows 32..59 are dead after phase 2).
    const int c2 = tid & 127;          // col pair 0..127
    const int g  = tid >> 7;           // row group 0/1
    const int o2 = swz2(XOFF + 2 * c2);
    const int rbase = g * 16;
    {
        float2 acc[16];
        #pragma unroll
        for (int j = 0; j < 16; ++j) acc[j] = make_float2(0.f, 0.f);

        #pragma unroll
        for (int i = 0; i < 44; ++i) {
            float2 v = *(const float2*)(&S[(rbase + i) * PITCH + o2]);
            #pragma unroll
            for (int j = 0; j < 16; ++j) {
                const int k = i - j;               // tap index
                if (k >= 0 && k <= 28) {
                    const float w = GW[k];
                    acc[j].x += w * v.x;
                    acc[j].y += w * v.y;
                }
            }
        }
        __syncthreads();   // all reads done everywhere
        #pragma unroll
        for (int j = 0; j < 16; ++j)
            *(float2*)(&S[(rbase + j) * PITCH + o2]) = acc[j];
        __syncthreads();   // writes visible before phases 2.5/3 read
    }

    // ---------------- Phase 2.5: horizontal reflected halo ------------------
    // Fill float cols [0,16) (xi=-16..-1 -> x=16..1) and [272,288)
    // (xi=256..271 -> x=254..239) for the 32 intermediate rows.
    #pragma unroll 4
    for (int u = tid; u < TY * 32; u += 256) {
        int r = u >> 5;
        int p = u & 31;
        int colidx, xsrc;
        if (p < 16) { colidx = p;                 xsrc = 16 - p;      }
        else        { int q = p - 16; colidx = XOFF + 256 + q; xsrc = 254 - q; }
        S[r * PITCH + swz2(colidx)] = S[r * PITCH + swz2(XOFF + xsrc)];
    }
    __syncthreads();

    // ---------------- Phase 3: horizontal 29-tap conv + store ---------------
    // 16 px/lane: half-warp per row (li = lane&15 covers px [16li,16li+16)).
    // Window floats o = 16*li .. 16*li+47 (12 quads); swz2 makes the 16-float
    // lane stride conflict-free. Chunked: 6 chunks of 8 floats, diagonal tap
    // order so m[] reuse stays in registers (~50 live regs).
    const int lane = tid & 31;
    const int warp = tid >> 5;         // 0..7
    const int li   = lane & 15;        // px group within row
    const int half = lane >> 4;        // row parity within warp
    #pragma unroll 1
    for (int it = 0; it < 2; ++it) {
        const int row = warp * 4 + it * 2 + half;   // 0..31
        const float* rb = &S[row * PITCH];

        float a[16];
        #pragma unroll
        for (int p = 0; p < 16; ++p) a[p] = 0.f;

        #pragma unroll
        for (int c = 0; c < 6; ++c) {
            const int o = 16 * li + 8 * c;          // window floats 8c..8c+7
            float4 va = *(const float4*)(rb + swz2(o));
            float4 vb = *(const float4*)(rb + swz2(o + 4));
            float m[8] = { va.x, va.y, va.z, va.w, vb.x, vb.y, vb.z, vb.w };

            // window idx = 8c + t ; a[p] needs idx p+k+2  =>  t = p + d,
            // d = k + 2 - 8c. Each (p,k) lands in exactly one chunk.
            #pragma unroll
            for (int d = -15; d <= 7; ++d) {
                const int k = 8 * c + d - 2;
                if (k >= 0 && k <= 28) {
                    const float w = GW[k];
                    #pragma unroll
                    for (int p = 0; p < 16; ++p) {
                        const int t = p + d;
                        if (t >= 0 && t < 8)
                            a[p] += w * m[t];
                    }
                }
            }
        }

        float* op = dst + (size_t)row * IMG_W + li * 16;
        *(float4*)(op +  0) = make_float4(a[0],  a[1],  a[2],  a[3]);
        *(float4*)(op +  4) = make_float4(a[4],  a[5],  a[6],  a[7]);
        *(float4*)(op +  8) = make_float4(a[8],  a[9],  a[10], a[11]);
        *(float4*)(op + 12) = make_float4(a[12], a[13], a[14], a[15]);
    }
}

extern "C" void kernel_launch(void* const* d_in, const int* in_sizes, int n_in,
                              void* d_out, int out_size)
{
    const float* x = (const float*)d_in[0];
    float* out = (float*)d_out;

    const int images = in_sizes[0] / (IMG_H * IMG_W);   // 512
    const int grid = images * 8;                        // 4096 CTAs

    cudaFuncSetAttribute(gauss29_kernel,
                         cudaFuncAttributeMaxDynamicSharedMemorySize,
                         SMEM_BYTES);
    gauss29_kernel<<<grid, 256, SMEM_BYTES>>>(x, out);
}